// round 7
// baseline (speedup 1.0000x reference)
#include <cuda_runtime.h>
#include <cuda_bf16.h>
#include <cstdint>
#include <cstddef>

#define B_    128
#define T_    512
#define IN_   64
#define H_    1024
#define OUT_  64

#define NCTA   128           // 4 b-groups x 32 h-groups
#define KP_REC 512           // recurrent k-pairs
#define KP_IN  32            // input k-pairs
#define KP_TOT (KP_REC + KP_IN)
#define NSLICE 16            // k-split (one warp per slice)

#define SW_PITCH   34        // u64 pitch for sW rows
#define SRED_PITCH 33        // float pitch for reduction rows (conflict-free)
#define SW_BYTES   (KP_TOT * SW_PITCH * 8)                 // 147968
#define SRED_BYTES (NSLICE * 32 * SRED_PITCH * 4)          // 67584
#define SMEM_RNN   (SW_BYTES + SRED_BYTES + 128)           // 215680

typedef unsigned long long u64;

// ---------------- static device scratch --------------------------------------
__device__ u64   g_frP[2][KP_REC][B_];     // fr state pair-packed [kp][b], ping-pong
__device__ u64   g_xP[T_][KP_IN][B_];      // input-proj operand pair-packed
__device__ u64   g_WoutP[KP_REC * OUT_];   // W_out pair-packed [kp][o]
__device__ unsigned g_arrive[4];           // per-b-group arrival counters
__device__ unsigned g_epoch[4];            // per-b-group released epochs

// ---------------- helpers -----------------------------------------------------
static __device__ __forceinline__ u64 pack2(float x, float y) {
    u64 r; asm("mov.b64 %0, {%1,%2};" : "=l"(r) : "f"(x), "f"(y)); return r;
}
static __device__ __forceinline__ float2 unpack2(u64 v) {
    float2 r; asm("mov.b64 {%0,%1}, %2;" : "=f"(r.x), "=f"(r.y) : "l"(v)); return r;
}
static __device__ __forceinline__ void fma2(u64& acc, u64 a, u64 b) {
    asm("fma.rn.f32x2 %0, %1, %2, %0;" : "+l"(acc) : "l"(a), "l"(b));
}
static __device__ __forceinline__ unsigned ld_acq(const unsigned* p) {
    unsigned v;
    asm volatile("ld.acquire.gpu.global.u32 %0, [%1];" : "=r"(v) : "l"(p));
    return v;
}
static __device__ __forceinline__ void st_rel(unsigned* p, unsigned v) {
    asm volatile("st.release.gpu.global.u32 [%0], %1;" :: "l"(p), "r"(v) : "memory");
}

// ============================================================================
// Prep: pack input-projection operand [T][KP_IN][B]
// ============================================================================
__global__ void k_prep_x(const float* __restrict__ inp) {
    int i = blockIdx.x * 256 + threadIdx.x;            // T_*KP_IN*B_ = 2097152
    if (i >= T_ * KP_IN * B_) return;
    int b  = i & 127;
    int kq = (i >> 7) & 31;
    int t  = i >> 12;
    const float* s = inp + ((size_t)b * T_ + t) * IN_ + 2 * kq;
    g_xP[t][kq][b] = pack2(s[0], s[1]);
}

// Prep: fr0 pack, W_out pair-pack, barrier reset
__global__ void k_prep_misc(const float* __restrict__ fr0,
                            const float* __restrict__ Woutw) {
    int i = blockIdx.x * 256 + threadIdx.x;            // 65536 threads
    {   // fr0 -> g_frP[0]
        int b = i & 127, hp = i >> 7;                  // hp < 512
        const float* s = fr0 + (size_t)b * H_ + 2 * hp;
        g_frP[0][hp][b] = pack2(s[0], s[1]);
    }
    if (i < KP_REC * OUT_) {                           // 32768
        int kp = i & 511, o = i >> 9;
        const float* s = Woutw + (size_t)o * H_ + 2 * kp;
        g_WoutP[(size_t)kp * OUT_ + o] = pack2(s[0], s[1]);
    }
    if (i < 4) { g_arrive[i] = 0u; g_epoch[i] = 0u; }
}

// ============================================================================
// Persistent recurrent loop: CTA = (bg 0..3) x (hg 0..31), 512 threads.
// Compute role: thread = (bl 0..31, kq 0..15); slice = 32 rec + 2 input k-pairs.
// Epilogue role: thread = (eb 0..31, h-pair 0..15).
// ============================================================================
__global__ void __launch_bounds__(512, 1)
k_rnn(const float* __restrict__ noise,
      const float* __restrict__ Winw,  const float* __restrict__ Winb,
      const float* __restrict__ Wrecw, const float* __restrict__ Wrecb,
      const float* __restrict__ fr0,
      float* __restrict__ out_rates)
{
    extern __shared__ unsigned char smem[];
    u64  (*sW)[SW_PITCH] = reinterpret_cast<u64(*)[SW_PITCH]>(smem);
    float* sRed = reinterpret_cast<float*>(smem + SW_BYTES);
    float* sB   = reinterpret_cast<float*>(smem + SW_BYTES + SRED_BYTES);

    const int tid = threadIdx.x;
    const int bg  = blockIdx.x & 3;
    const int hg  = blockIdx.x >> 2;
    const int h0  = hg * 32;
    const int b0  = bg * 32;

    // ---- stage pair-packed weight slice sW[kp][h'] ---------------------------
    {
        const int lane = tid & 31;
        for (int h = tid >> 5; h < 32; h += NSLICE) {
            const float* wr = Wrecw + (size_t)(h0 + h) * H_;
            for (int kp = lane; kp < KP_REC; kp += 32) {
                float2 v = *reinterpret_cast<const float2*>(wr + 2 * kp);
                sW[kp][h] = pack2(v.x, v.y);
            }
            const float* wi = Winw + (size_t)(h0 + h) * IN_;
            float2 v = *reinterpret_cast<const float2*>(wi + 2 * lane);
            sW[KP_REC + lane][h] = pack2(v.x, v.y);
        }
        if (tid < 32) sB[tid] = Winb[h0 + tid] + Wrecb[h0 + tid];
    }

    // ---- epilogue role: thread owns (eb, eh..eh+1), fr kept in registers ----
    const int eb  = tid >> 4;            // 0..31
    const int eh  = (tid & 15) * 2;      // 0,2,..,30
    const int ebg = b0 + eb;
    const int ehg = h0 + eh;
    float fr_a, fr_b;
    {
        float2 f = *reinterpret_cast<const float2*>(fr0 + (size_t)ebg * H_ + ehg);
        fr_a = f.x; fr_b = f.y;
    }
    __syncthreads();

    const int bl    = tid & 31;          // compute-role local batch
    const int kq    = tid >> 5;          // compute-role k slice (0..15)
    const int bglob = b0 + bl;
    const int kb    = kq * 32;           // first rec k-pair of this slice

    for (int t = 0; t < T_; ++t) {
        const u64* cur = &g_frP[t & 1][0][0];
        u64*       nxt = &g_frP[(t + 1) & 1][0][0];

        u64 acc[32];
        #pragma unroll
        for (int j = 0; j < 32; ++j) acc[j] = 0ull;

        // recurrent part: 32 k-pairs
        {
            const u64* p = cur + (size_t)kb * B_ + bglob;
            #pragma unroll 4
            for (int i = 0; i < 32; ++i) {
                u64 fr2 = __ldcg(p + (size_t)i * B_);
                const ulonglong2* w =
                    reinterpret_cast<const ulonglong2*>(&sW[kb + i][0]);
                #pragma unroll
                for (int q = 0; q < 16; ++q) {
                    ulonglong2 ww = w[q];
                    fma2(acc[2 * q],     fr2, ww.x);
                    fma2(acc[2 * q + 1], fr2, ww.y);
                }
            }
        }
        // input-projection part: 2 k-pairs
        {
            #pragma unroll
            for (int j = 0; j < 2; ++j) {
                u64 x2 = __ldcg(&g_xP[t][kq * 2 + j][0] + bglob);
                const ulonglong2* w =
                    reinterpret_cast<const ulonglong2*>(&sW[KP_REC + kq * 2 + j][0]);
                #pragma unroll
                for (int q = 0; q < 16; ++q) {
                    ulonglong2 ww = w[q];
                    fma2(acc[2 * q],     x2, ww.x);
                    fma2(acc[2 * q + 1], x2, ww.y);
                }
            }
        }
        // pair-sum -> reduction smem
        {
            float* dst = sRed + ((size_t)(kb + bl)) * SRED_PITCH;
            #pragma unroll
            for (int h = 0; h < 32; ++h) {
                float2 v = unpack2(acc[h]);
                dst[h] = v.x + v.y;
            }
        }
        __syncthreads();

        // ---- epilogue: 16-way k reduce, bias+noise, tanh, leaky update ------
        {
            float s0 = 0.f, s1 = 0.f;
            #pragma unroll
            for (int q = 0; q < NSLICE; ++q) {
                const float* src = sRed + ((size_t)(q * 32 + eb)) * SRED_PITCH + eh;
                s0 += src[0]; s1 += src[1];
            }
            float2 n = *reinterpret_cast<const float2*>(
                noise + ((size_t)t * B_ + ebg) * H_ + ehg);

            fr_a = 0.9f * fr_a + 0.1f * tanhf(s0 + sB[eh + 0] + n.x);
            fr_b = 0.9f * fr_b + 0.1f * tanhf(s1 + sB[eh + 1] + n.y);

            __stcg(nxt + (size_t)(ehg >> 1) * B_ + ebg, pack2(fr_a, fr_b));
            *reinterpret_cast<float2*>(
                out_rates + ((size_t)ebg * T_ + t) * H_ + ehg) =
                make_float2(fr_a, fr_b);
        }

        // ---- per-b-group grid barrier (32 CTAs) -----------------------------
        if (t < T_ - 1) {
            __threadfence();
            __syncthreads();
            if (tid == 0) {
                unsigned old = atomicAdd(&g_arrive[bg], 1u);
                if (old == 32u * (unsigned)(t + 1) - 1u) {
                    st_rel(&g_epoch[bg], (unsigned)(t + 1));
                } else {
                    while (ld_acq(&g_epoch[bg]) < (unsigned)(t + 1)) {}
                }
            }
            __syncthreads();
        }
    }
}

// ============================================================================
// preds: sigmoid(fr_{t-1} @ Wout^T + b). Tiled GEMM: 64 rows x 64 outs/block.
// ============================================================================
#define PR_CH    32                    // k-pairs per chunk
#define PR_PITCH 66                    // u64 pitch

__global__ void __launch_bounds__(256)
k_preds(const float* __restrict__ fr0,
        const float* __restrict__ Woutb,
        const float* __restrict__ rates,
        float* __restrict__ preds)
{
    __shared__ __align__(16) u64 sFr[PR_CH][PR_PITCH];
    __shared__ __align__(16) u64 sWo[PR_CH][PR_PITCH];

    const int tid  = threadIdx.x;
    const int rx   = tid >> 4;
    const int ox   = tid & 15;
    const int row0 = blockIdx.x * 64;

    u64 acc[16];
    #pragma unroll
    for (int j = 0; j < 16; ++j) acc[j] = 0ull;

    for (int c = 0; c < KP_REC / PR_CH; ++c) {
        #pragma unroll
        for (int it = 0; it < 4; ++it) {
            int i  = tid + it * 256;
            int f4 = i & 15, r = i >> 4;
            int row = row0 + r;
            int bb = row >> 9, tt = row & (T_ - 1);
            const float4* src = (tt == 0)
                ? reinterpret_cast<const float4*>(fr0 + (size_t)bb * H_)
                : reinterpret_cast<const float4*>(
                      rates + ((size_t)bb * T_ + (tt - 1)) * H_);
            float4 v = src[c * 16 + f4];
            sFr[f4 * 2][r]     = pack2(v.x, v.y);
            sFr[f4 * 2 + 1][r] = pack2(v.z, v.w);
        }
        #pragma unroll
        for (int it = 0; it < 4; ++it) {
            int i   = tid + it * 256;
            int u2  = i & 31, kpl = i >> 5;
            ulonglong2 v = *reinterpret_cast<const ulonglong2*>(
                &g_WoutP[(size_t)(c * PR_CH + kpl) * OUT_ + u2 * 2]);
            *reinterpret_cast<ulonglong2*>(&sWo[kpl][u2 * 2]) = v;
        }
        __syncthreads();

        #pragma unroll 4
        for (int kpl = 0; kpl < PR_CH; ++kpl) {
            ulonglong2 f01 = *reinterpret_cast<const ulonglong2*>(&sFr[kpl][rx * 4]);
            ulonglong2 f23 = *reinterpret_cast<const ulonglong2*>(&sFr[kpl][rx * 4 + 2]);
            ulonglong2 w01 = *reinterpret_cast<const ulonglong2*>(&sWo[kpl][ox * 4]);
            ulonglong2 w23 = *reinterpret_cast<const ulonglong2*>(&sWo[kpl][ox * 4 + 2]);
            u64 fr2[4] = {f01.x, f01.y, f23.x, f23.y};
            u64 wo2[4] = {w01.x, w01.y, w23.x, w23.y};
            #pragma unroll
            for (int a = 0; a < 4; ++a)
                #pragma unroll
                for (int o = 0; o < 4; ++o)
                    fma2(acc[a * 4 + o], fr2[a], wo2[o]);
        }
        __syncthreads();
    }

    float bias[4];
    #pragma unroll
    for (int o = 0; o < 4; ++o) bias[o] = Woutb[ox * 4 + o];
    #pragma unroll
    for (int a = 0; a < 4; ++a) {
        float4 v;
        float* vp = reinterpret_cast<float*>(&v);
        #pragma unroll
        for (int o = 0; o < 4; ++o) {
            float2 p = unpack2(acc[a * 4 + o]);
            float z = p.x + p.y + bias[o];
            vp[o] = 1.0f / (1.0f + __expf(-z));
        }
        int row = row0 + rx * 4 + a;
        *reinterpret_cast<float4*>(preds + (size_t)row * OUT_ + ox * 4) = v;
    }
}

// ============================================================================
extern "C" void kernel_launch(void* const* d_in, const int* in_sizes, int n_in,
                              void* d_out, int out_size) {
    (void)in_sizes; (void)n_in; (void)out_size;
    const float* inp   = (const float*)d_in[0];
    const float* fr0   = (const float*)d_in[1];
    const float* noise = (const float*)d_in[2];
    const float* Winw  = (const float*)d_in[3];
    const float* Winb  = (const float*)d_in[4];
    const float* Wrecw = (const float*)d_in[5];
    const float* Wrecb = (const float*)d_in[6];
    const float* Woutw = (const float*)d_in[7];
    const float* Woutb = (const float*)d_in[8];

    float* out   = (float*)d_out;
    float* preds = out;                                   // [B,T,OUT]
    float* rates = out + (size_t)B_ * T_ * OUT_;          // [B,T,H]

    static bool attr_set = false;
    if (!attr_set) {
        cudaFuncSetAttribute(k_rnn, cudaFuncAttributeMaxDynamicSharedMemorySize,
                             SMEM_RNN);
        attr_set = true;
    }

    k_prep_x<<<(T_ * KP_IN * B_) / 256, 256>>>(inp);
    k_prep_misc<<<(H_ / 2 * B_) / 256, 256>>>(fr0, Woutw);
    k_rnn<<<NCTA, 512, SMEM_RNN>>>(noise, Winw, Winb, Wrecw, Wrecb, fr0, rates);
    k_preds<<<(B_ * T_) / 64, 256>>>(fr0, Woutb, rates, preds);
}